// round 4
// baseline (speedup 1.0000x reference)
#include <cuda_runtime.h>
#include <cuda_bf16.h>

#define D 256
#define NS 16
#define B_ROWS 131072
#define GRID_MAIN 152
#define LN_EPS 1e-5f
#define ATT_EPS 1e-8f
#define SCALE 0.0625f

// ---------------- device scratch (static; no runtime allocation) ----------------
__device__ float g_slots[NS * D];
__device__ float g_qk[NS * D];
__device__ float g_cn[NS];
__device__ float g_updates[NS * D];
__device__ float g_partU[GRID_MAIN * NS * D];
__device__ float g_partS[GRID_MAIN * NS];

// ---------------- helpers ----------------
__device__ __forceinline__ float warp_sum(float v) {
    v += __shfl_xor_sync(0xffffffffu, v, 16);
    v += __shfl_xor_sync(0xffffffffu, v, 8);
    v += __shfl_xor_sync(0xffffffffu, v, 4);
    v += __shfl_xor_sync(0xffffffffu, v, 2);
    v += __shfl_xor_sync(0xffffffffu, v, 1);
    return v;
}

// blockDim.x == 256
__device__ __forceinline__ float block_sum256(float v, float* red) {
    const int lane = threadIdx.x & 31;
    const int w = threadIdx.x >> 5;
    v = warp_sum(v);
    if (lane == 0) red[w] = v;
    __syncthreads();
    if (w == 0) {
        float x = (lane < 8) ? red[lane] : 0.0f;
        x += __shfl_xor_sync(0xffffffffu, x, 4);
        x += __shfl_xor_sync(0xffffffffu, x, 2);
        x += __shfl_xor_sync(0xffffffffu, x, 1);
        if (lane == 0) red[0] = x;
    }
    __syncthreads();
    float r = red[0];
    __syncthreads();
    return r;
}

__device__ __forceinline__ float dot4(float4 a, float4 b) {
    return a.x * b.x + a.y * b.y + a.z * b.z + a.w * b.w;
}

__device__ __forceinline__ unsigned long long pack2(float lo, float hi) {
    unsigned long long r;
    asm("mov.b64 %0, {%1, %2};" : "=l"(r) : "f"(lo), "f"(hi));
    return r;
}
__device__ __forceinline__ void unpack2(unsigned long long v, float& lo, float& hi) {
    asm("mov.b64 {%0, %1}, %2;" : "=f"(lo), "=f"(hi) : "l"(v));
}
// d += a * b elementwise on packed fp32 pairs (sm_103a)
__device__ __forceinline__ void fma2(unsigned long long& d, unsigned long long a, unsigned long long b) {
    asm("fma.rn.f32x2 %0, %1, %2, %0;" : "+l"(d) : "l"(a), "l"(b));
}

__device__ __forceinline__ float sigmoidf_(float x) { return 1.0f / (1.0f + expf(-x)); }

// ---------------- K0: slots init ----------------
__global__ void k_init_slots(const float* __restrict__ noise,
                             const float* __restrict__ mu,
                             const float* __restrict__ sigma) {
    const int n = blockIdx.x, t = threadIdx.x;
    g_slots[n * D + t] = mu[t] + sigma[t] * noise[n * D + t];
}

// ---------------- K1: per-iter prep: s=LN(slots), q=s@Wq.T+bq, qk=scale*q@Wk, cn=scale*q.bk ----------------
__global__ void k_prep(const float* __restrict__ Wq, const float* __restrict__ bq,
                       const float* __restrict__ Wk, const float* __restrict__ bk,
                       const float* __restrict__ gs, const float* __restrict__ bes) {
    __shared__ __align__(16) float s_sh[D];
    __shared__ __align__(16) float q_sh[D];
    __shared__ float red[32];
    const int n = blockIdx.x, t = threadIdx.x;

    const float sv = g_slots[n * D + t];
    const float m = block_sum256(sv, red) * (1.0f / (float)D);
    const float dv = sv - m;
    const float var = block_sum256(dv * dv, red) * (1.0f / (float)D);
    const float rstd = rsqrtf(var + LN_EPS);
    s_sh[t] = dv * rstd * gs[t] + bes[t];
    __syncthreads();

    // q[t] = bq[t] + Wq[t,:] . s
    {
        const float4* wq4 = reinterpret_cast<const float4*>(Wq + (size_t)t * D);
        const float4* s4 = reinterpret_cast<const float4*>(s_sh);
        float acc = bq[t];
#pragma unroll 8
        for (int i = 0; i < D / 4; i++) acc += dot4(wq4[i], s4[i]);
        q_sh[t] = acc;
    }
    __syncthreads();

    // qk[n,t] = SCALE * sum_i q[i] * Wk[i,t]
    {
        float acc = 0.0f;
#pragma unroll 8
        for (int i = 0; i < D; i++) acc += q_sh[i] * Wk[(size_t)i * D + t];
        g_qk[n * D + t] = acc * SCALE;
    }
    // cn[n] = SCALE * q . bk
    {
        const float p = block_sum256(q_sh[t] * bk[t], red);
        if (t == 0) g_cn[n] = p * SCALE;
    }
}

// ---------------- K2: fused main pass ----------------
// Per row b (one warp per row, grid-strided): LN(x[b]) in regs -> 16 dots -> softmax(+eps)
// -> S[n] += attn[n]; U[n][c] += attn[n]*xl[c] (register-resident, packed fp32x2 FMA).
__global__ void __launch_bounds__(256, 1)
k_main(const float* __restrict__ x,
       const float* __restrict__ gin, const float* __restrict__ bin) {
    __shared__ __align__(16) float qk_s[NS * D];
    __shared__ float cn_s[NS];
    __shared__ __align__(16) float ublk[NS * D];
    __shared__ float sblk[8][NS];

    const int tid = threadIdx.x;
    const int lane = tid & 31;
    const int warp = tid >> 5;

    for (int i = tid; i < NS * D; i += 256) qk_s[i] = g_qk[i];
    if (tid < NS) cn_s[tid] = g_cn[tid];
    __syncthreads();

    // per-lane LN affine (lane owns float4 indices {lane, lane+32} of each row)
    const float4* gin4 = reinterpret_cast<const float4*>(gin);
    const float4* bin4 = reinterpret_cast<const float4*>(bin);
    const float4 gv0 = gin4[lane], gv1 = gin4[lane + 32];
    const float4 bb0 = bin4[lane], bb1 = bin4[lane + 32];

    unsigned long long u2[NS][4];
#pragma unroll
    for (int n = 0; n < NS; n++)
#pragma unroll
        for (int p = 0; p < 4; p++) u2[n][p] = 0ull;
    float s_acc[NS];
#pragma unroll
    for (int n = 0; n < NS; n++) s_acc[n] = 0.0f;

    const int gw = blockIdx.x * 8 + warp;
    const int TOTW = GRID_MAIN * 8;
    const float4* x4 = reinterpret_cast<const float4*>(x);

    for (int r = gw; r < B_ROWS; r += TOTW) {
        const float4 v0 = x4[r * 64 + lane];
        const float4 v1 = x4[r * 64 + 32 + lane];
        float sm = v0.x + v0.y + v0.z + v0.w + v1.x + v1.y + v1.z + v1.w;
        float sq = v0.x * v0.x + v0.y * v0.y + v0.z * v0.z + v0.w * v0.w
                 + v1.x * v1.x + v1.y * v1.y + v1.z * v1.z + v1.w * v1.w;
        sm = warp_sum(sm);
        sq = warp_sum(sq);
        const float mean = sm * (1.0f / 256.0f);
        const float var = fmaxf(sq * (1.0f / 256.0f) - mean * mean, 0.0f);
        const float rstd = rsqrtf(var + LN_EPS);

        float xlv[8];
        xlv[0] = (v0.x - mean) * rstd * gv0.x + bb0.x;
        xlv[1] = (v0.y - mean) * rstd * gv0.y + bb0.y;
        xlv[2] = (v0.z - mean) * rstd * gv0.z + bb0.z;
        xlv[3] = (v0.w - mean) * rstd * gv0.w + bb0.w;
        xlv[4] = (v1.x - mean) * rstd * gv1.x + bb1.x;
        xlv[5] = (v1.y - mean) * rstd * gv1.y + bb1.y;
        xlv[6] = (v1.z - mean) * rstd * gv1.z + bb1.z;
        xlv[7] = (v1.w - mean) * rstd * gv1.w + bb1.w;

        unsigned long long xl2[4];
        xl2[0] = pack2(xlv[0], xlv[1]);
        xl2[1] = pack2(xlv[2], xlv[3]);
        xl2[2] = pack2(xlv[4], xlv[5]);
        xl2[3] = pack2(xlv[6], xlv[7]);

        // dots: lane-partial over its 8 cols, then warp reduce
        float d[NS];
#pragma unroll
        for (int n = 0; n < NS; n++) {
            const float4 qa = *reinterpret_cast<const float4*>(qk_s + n * D + lane * 4);
            const float4 qb = *reinterpret_cast<const float4*>(qk_s + n * D + 128 + lane * 4);
            d[n] = qa.x * xlv[0] + qa.y * xlv[1] + qa.z * xlv[2] + qa.w * xlv[3]
                 + qb.x * xlv[4] + qb.y * xlv[5] + qb.z * xlv[6] + qb.w * xlv[7];
        }
#pragma unroll
        for (int n = 0; n < NS; n++) d[n] = warp_sum(d[n]) + cn_s[n];

        // softmax over 16 slots (replicated per lane)
        float mx = d[0];
#pragma unroll
        for (int n = 1; n < NS; n++) mx = fmaxf(mx, d[n]);
        float ssum = 0.0f;
#pragma unroll
        for (int n = 0; n < NS; n++) { d[n] = __expf(d[n] - mx); ssum += d[n]; }
        const float inv = 1.0f / ssum;

#pragma unroll
        for (int n = 0; n < NS; n++) {
            const float a = d[n] * inv + ATT_EPS;
            s_acc[n] += a;
            const unsigned long long a2 = pack2(a, a);
            fma2(u2[n][0], a2, xl2[0]);
            fma2(u2[n][1], a2, xl2[1]);
            fma2(u2[n][2], a2, xl2[2]);
            fma2(u2[n][3], a2, xl2[3]);
        }
    }

    // stage per-warp partials into shared (serialized, deterministic)
    for (int w = 0; w < 8; w++) {
        if (warp == w) {
#pragma unroll
            for (int n = 0; n < NS; n++) {
#pragma unroll
                for (int p = 0; p < 4; p++) {
                    float lo, hi;
                    unpack2(u2[n][p], lo, hi);
                    const int c = (p < 2) ? (lane * 4 + 2 * p) : (128 + lane * 4 + 2 * (p - 2));
                    if (w == 0) {
                        ublk[n * D + c] = lo;
                        ublk[n * D + c + 1] = hi;
                    } else {
                        ublk[n * D + c] += lo;
                        ublk[n * D + c + 1] += hi;
                    }
                }
            }
            if (lane == 0) {
#pragma unroll
                for (int n = 0; n < NS; n++) sblk[w][n] = s_acc[n];
            }
        }
        __syncthreads();
    }

    for (int i = tid; i < NS * D; i += 256)
        g_partU[(size_t)blockIdx.x * (NS * D) + i] = ublk[i];
    if (tid < NS) {
        float t = 0.0f;
#pragma unroll
        for (int w = 0; w < 8; w++) t += sblk[w][tid];
        g_partS[blockIdx.x * NS + tid] = t;
    }
}

// ---------------- K3: reduce partials, normalize, apply Wv ----------------
__global__ void k_reduce_update(const float* __restrict__ Wv, const float* __restrict__ bv) {
    __shared__ __align__(16) float un[D];
    __shared__ float red[32];
    const int n = blockIdx.x, t = threadIdx.x;

    const float sv = (t < GRID_MAIN) ? g_partS[t * NS + n] : 0.0f;
    const float S = block_sum256(sv, red);

    float uacc = 0.0f;
    for (int k = 0; k < GRID_MAIN; k++)
        uacc += g_partU[(size_t)k * (NS * D) + n * D + t];
    un[t] = uacc / S;
    __syncthreads();

    const float4* w4 = reinterpret_cast<const float4*>(Wv + (size_t)t * D);
    const float4* u4 = reinterpret_cast<const float4*>(un);
    float acc = bv[t];
#pragma unroll 8
    for (int i = 0; i < D / 4; i++) acc += dot4(w4[i], u4[i]);
    g_updates[n * D + t] = acc;
}

// ---------------- K4: GRU cell + LN + FFN residual ----------------
__global__ void k_gru(const float* __restrict__ W_ih, const float* __restrict__ W_hh,
                      const float* __restrict__ b_ih, const float* __restrict__ b_hh,
                      const float* __restrict__ W1, const float* __restrict__ b1,
                      const float* __restrict__ W2, const float* __restrict__ b2,
                      const float* __restrict__ gf, const float* __restrict__ bef,
                      float* __restrict__ out, int write_out) {
    __shared__ __align__(16) float up_s[D];
    __shared__ __align__(16) float h_s[D];
    __shared__ __align__(16) float tmp_s[D];
    __shared__ float red[32];
    const int n = blockIdx.x, t = threadIdx.x;

    up_s[t] = g_updates[n * D + t];
    h_s[t] = g_slots[n * D + t];
    __syncthreads();

    const float4* u4 = reinterpret_cast<const float4*>(up_s);
    const float4* h4 = reinterpret_cast<const float4*>(h_s);

    float gx[3], gh[3];
#pragma unroll
    for (int gi = 0; gi < 3; gi++) {
        const float4* wx = reinterpret_cast<const float4*>(W_ih + (size_t)(gi * D + t) * D);
        const float4* wh = reinterpret_cast<const float4*>(W_hh + (size_t)(gi * D + t) * D);
        float ax = b_ih[gi * D + t];
        float ah = b_hh[gi * D + t];
#pragma unroll 4
        for (int i = 0; i < D / 4; i++) {
            ax += dot4(wx[i], u4[i]);
            ah += dot4(wh[i], h4[i]);
        }
        gx[gi] = ax;
        gh[gi] = ah;
    }

    const float r = sigmoidf_(gx[0] + gh[0]);
    const float z = sigmoidf_(gx[1] + gh[1]);
    const float nn = tanhf(gx[2] + r * gh[2]);
    const float hnew = (1.0f - z) * nn + z * h_s[t];

    // LN(hnew)
    const float m = block_sum256(hnew, red) * (1.0f / (float)D);
    const float dv = hnew - m;
    const float var = block_sum256(dv * dv, red) * (1.0f / (float)D);
    const float lnf = dv * rsqrtf(var + LN_EPS) * gf[t] + bef[t];
    tmp_s[t] = lnf;
    __syncthreads();

    // hidden = relu(W1 @ lnf + b1)
    const float4* l4 = reinterpret_cast<const float4*>(tmp_s);
    const float4* w1r = reinterpret_cast<const float4*>(W1 + (size_t)t * D);
    float hd = b1[t];
#pragma unroll 8
    for (int i = 0; i < D / 4; i++) hd += dot4(w1r[i], l4[i]);
    hd = fmaxf(hd, 0.0f);
    __syncthreads();
    tmp_s[t] = hd;
    __syncthreads();

    // o = W2 @ hidden + b2 ; slots = hnew + o
    const float4* hh4 = reinterpret_cast<const float4*>(tmp_s);
    const float4* w2r = reinterpret_cast<const float4*>(W2 + (size_t)t * D);
    float o = b2[t];
#pragma unroll 8
    for (int i = 0; i < D / 4; i++) o += dot4(w2r[i], hh4[i]);

    const float res = hnew + o;
    g_slots[n * D + t] = res;
    if (write_out) out[n * D + t] = res;
}

// ---------------- launch ----------------
extern "C" void kernel_launch(void* const* d_in, const int* in_sizes, int n_in,
                              void* d_out, int out_size) {
    const float* x      = (const float*)d_in[0];
    const float* noise  = (const float*)d_in[1];
    const float* mu     = (const float*)d_in[2];
    const float* sigma  = (const float*)d_in[3];
    const float* Wq     = (const float*)d_in[4];
    const float* bq     = (const float*)d_in[5];
    const float* Wk     = (const float*)d_in[6];
    const float* bk     = (const float*)d_in[7];
    const float* Wv     = (const float*)d_in[8];
    const float* bv     = (const float*)d_in[9];
    const float* W_ih   = (const float*)d_in[10];
    const float* W_hh   = (const float*)d_in[11];
    const float* b_ih   = (const float*)d_in[12];
    const float* b_hh   = (const float*)d_in[13];
    const float* W1     = (const float*)d_in[14];
    const float* b1     = (const float*)d_in[15];
    const float* W2     = (const float*)d_in[16];
    const float* b2     = (const float*)d_in[17];
    const float* g_in   = (const float*)d_in[18];
    const float* be_in  = (const float*)d_in[19];
    const float* g_s    = (const float*)d_in[20];
    const float* be_s   = (const float*)d_in[21];
    const float* g_f    = (const float*)d_in[22];
    const float* be_f   = (const float*)d_in[23];
    float* out = (float*)d_out;

    k_init_slots<<<NS, D>>>(noise, mu, sigma);
    for (int it = 0; it < 3; it++) {
        k_prep<<<NS, D>>>(Wq, bq, Wk, bk, g_s, be_s);
        k_main<<<GRID_MAIN, 256>>>(x, g_in, be_in);
        k_reduce_update<<<NS, D>>>(Wv, bv);
        k_gru<<<NS, D>>>(W_ih, W_hh, b_ih, b_hh, W1, b1, W2, b2, g_f, be_f,
                         out, it == 2 ? 1 : 0);
    }
}

// round 5
// speedup vs baseline: 1.0778x; 1.0778x over previous
#include <cuda_runtime.h>
#include <cuda_bf16.h>

#define D 256
#define NS 16
#define B_ROWS 131072
#define GRID_MAIN 148
#define TOTW (GRID_MAIN * 8)
#define LN_EPS 1e-5f
#define ATT_EPS 1e-8f
#define SCALE 0.0625f

typedef unsigned long long ull;

// ---------------- device scratch (static; no runtime allocation) ----------------
__device__ float g_slots[NS * D];
__device__ float g_qk[NS * D];
__device__ float g_cn[NS];
__device__ float g_attn[(size_t)B_ROWS * NS];
__device__ float g_partU[GRID_MAIN * NS * D];
__device__ float g_partS[GRID_MAIN * NS];

// ---------------- helpers ----------------
__device__ __forceinline__ float warp_sum(float v) {
    v += __shfl_xor_sync(0xffffffffu, v, 16);
    v += __shfl_xor_sync(0xffffffffu, v, 8);
    v += __shfl_xor_sync(0xffffffffu, v, 4);
    v += __shfl_xor_sync(0xffffffffu, v, 2);
    v += __shfl_xor_sync(0xffffffffu, v, 1);
    return v;
}

// blockDim.x == 256
__device__ __forceinline__ float block_sum256(float v, float* red) {
    const int lane = threadIdx.x & 31;
    const int w = threadIdx.x >> 5;
    v = warp_sum(v);
    if (lane == 0) red[w] = v;
    __syncthreads();
    if (w == 0) {
        float x = (lane < 8) ? red[lane] : 0.0f;
        x += __shfl_xor_sync(0xffffffffu, x, 4);
        x += __shfl_xor_sync(0xffffffffu, x, 2);
        x += __shfl_xor_sync(0xffffffffu, x, 1);
        if (lane == 0) red[0] = x;
    }
    __syncthreads();
    float r = red[0];
    __syncthreads();
    return r;
}

__device__ __forceinline__ float dot4(float4 a, float4 b) {
    return a.x * b.x + a.y * b.y + a.z * b.z + a.w * b.w;
}

__device__ __forceinline__ ull pack2(float lo, float hi) {
    ull r;
    asm("mov.b64 %0, {%1, %2};" : "=l"(r) : "f"(lo), "f"(hi));
    return r;
}
__device__ __forceinline__ void unpack2(ull v, float& lo, float& hi) {
    asm("mov.b64 {%0, %1}, %2;" : "=f"(lo), "=f"(hi) : "l"(v));
}
// d += a * b elementwise on packed fp32 pairs (sm_103a)
__device__ __forceinline__ void fma2(ull& d, ull a, ull b) {
    asm("fma.rn.f32x2 %0, %1, %2, %0;" : "+l"(d) : "l"(a), "l"(b));
}

__device__ __forceinline__ float sigmoidf_(float x) { return 1.0f / (1.0f + expf(-x)); }

// ---------------- prep body: s=LN(slots_val), q=s@Wq.T+bq, qk=SCALE*q@Wk, cn=SCALE*q.bk ----
// grid.x = NS blocks of 256 threads; sv = this (n,t)'s slot value (already in register).
__device__ __forceinline__ void prep_body(int n, int t, float sv,
                                          const float* __restrict__ Wq, const float* __restrict__ bq,
                                          const float* __restrict__ Wk, const float* __restrict__ bk,
                                          const float* __restrict__ gs, const float* __restrict__ bes,
                                          float* s_sh, float* q_sh, float* red) {
    const float m = block_sum256(sv, red) * (1.0f / (float)D);
    const float dv = sv - m;
    const float var = block_sum256(dv * dv, red) * (1.0f / (float)D);
    const float rstd = rsqrtf(var + LN_EPS);
    s_sh[t] = dv * rstd * gs[t] + bes[t];
    __syncthreads();

    // q[t] = bq[t] + Wq[t,:] . s
    {
        const float4* wq4 = reinterpret_cast<const float4*>(Wq + (size_t)t * D);
        const float4* s4 = reinterpret_cast<const float4*>(s_sh);
        float a0 = bq[t], a1 = 0.0f, a2 = 0.0f, a3 = 0.0f;
#pragma unroll 4
        for (int i = 0; i < D / 4; i += 4) {
            a0 += dot4(wq4[i], s4[i]);
            a1 += dot4(wq4[i + 1], s4[i + 1]);
            a2 += dot4(wq4[i + 2], s4[i + 2]);
            a3 += dot4(wq4[i + 3], s4[i + 3]);
        }
        q_sh[t] = (a0 + a1) + (a2 + a3);
    }
    __syncthreads();

    // qk[n,t] = SCALE * sum_i q[i] * Wk[i,t]   (coalesced over t)
    {
        float a0 = 0.0f, a1 = 0.0f, a2 = 0.0f, a3 = 0.0f;
#pragma unroll 4
        for (int i = 0; i < D; i += 4) {
            a0 += q_sh[i] * Wk[(size_t)i * D + t];
            a1 += q_sh[i + 1] * Wk[(size_t)(i + 1) * D + t];
            a2 += q_sh[i + 2] * Wk[(size_t)(i + 2) * D + t];
            a3 += q_sh[i + 3] * Wk[(size_t)(i + 3) * D + t];
        }
        g_qk[n * D + t] = ((a0 + a1) + (a2 + a3)) * SCALE;
    }
    // cn[n] = SCALE * q . bk
    {
        const float p = block_sum256(q_sh[t] * bk[t], red);
        if (t == 0) g_cn[n] = p * SCALE;
    }
}

// ---------------- K_pre: slots init + first prep ----------------
__global__ void k_pre(const float* __restrict__ noise, const float* __restrict__ mu,
                      const float* __restrict__ sigma,
                      const float* __restrict__ Wq, const float* __restrict__ bq,
                      const float* __restrict__ Wk, const float* __restrict__ bk,
                      const float* __restrict__ gs, const float* __restrict__ bes) {
    __shared__ __align__(16) float s_sh[D];
    __shared__ __align__(16) float q_sh[D];
    __shared__ float red[32];
    const int n = blockIdx.x, t = threadIdx.x;
    const float sv = mu[t] + sigma[t] * noise[n * D + t];
    g_slots[n * D + t] = sv;
    prep_body(n, t, sv, Wq, bq, Wk, bk, gs, bes, s_sh, q_sh, red);
}

// ---------------- K_dots: per-row LN -> 16 dots (qk in regs) -> softmax -> attn out ----
__global__ void __launch_bounds__(256, 1)
k_dots(const float* __restrict__ x,
       const float* __restrict__ gin, const float* __restrict__ bin) {
    const int tid = threadIdx.x;
    const int lane = tid & 31;
    const int warp = tid >> 5;
    const int sigma = __brev((unsigned)(lane & 15)) >> 28;  // bitrev4

    // qk into registers: lane owns cols {4l..4l+3, 128+4l..128+4l+3} per slot, packed
    ull qk2[NS][4];
    {
        const float4* qk4g = reinterpret_cast<const float4*>(g_qk);
#pragma unroll
        for (int n = 0; n < NS; n++) {
            const float4 qa = qk4g[n * 64 + lane];
            const float4 qb = qk4g[n * 64 + 32 + lane];
            qk2[n][0] = pack2(qa.x, qa.y);
            qk2[n][1] = pack2(qa.z, qa.w);
            qk2[n][2] = pack2(qb.x, qb.y);
            qk2[n][3] = pack2(qb.z, qb.w);
        }
    }
    const float cn_r = g_cn[sigma];

    const float4* gin4 = reinterpret_cast<const float4*>(gin);
    const float4* bin4 = reinterpret_cast<const float4*>(bin);
    const float4 gv0 = gin4[lane], gv1 = gin4[lane + 32];
    const float4 bb0 = bin4[lane], bb1 = bin4[lane + 32];

    const float4* x4 = reinterpret_cast<const float4*>(x);
    int r = blockIdx.x * 8 + warp;

    float4 v0 = x4[r * 64 + lane];
    float4 v1 = x4[r * 64 + 32 + lane];

    while (true) {
        const int rn = r + TOTW;
        const bool more = rn < B_ROWS;
        const int rl = more ? rn : r;
        const float4 n0 = x4[rl * 64 + lane];
        const float4 n1 = x4[rl * 64 + 32 + lane];

        // ---- LayerNorm in registers ----
        float sm = v0.x + v0.y + v0.z + v0.w + v1.x + v1.y + v1.z + v1.w;
        float sq = v0.x * v0.x + v0.y * v0.y + v0.z * v0.z + v0.w * v0.w
                 + v1.x * v1.x + v1.y * v1.y + v1.z * v1.z + v1.w * v1.w;
        sm = warp_sum(sm);
        sq = warp_sum(sq);
        const float mean = sm * (1.0f / 256.0f);
        const float var = fmaxf(sq * (1.0f / 256.0f) - mean * mean, 0.0f);
        const float rstd = rsqrtf(var + LN_EPS);

        ull xl2[4];
        xl2[0] = pack2((v0.x - mean) * rstd * gv0.x + bb0.x, (v0.y - mean) * rstd * gv0.y + bb0.y);
        xl2[1] = pack2((v0.z - mean) * rstd * gv0.z + bb0.z, (v0.w - mean) * rstd * gv0.w + bb0.w);
        xl2[2] = pack2((v1.x - mean) * rstd * gv1.x + bb1.x, (v1.y - mean) * rstd * gv1.y + bb1.y);
        xl2[3] = pack2((v1.z - mean) * rstd * gv1.z + bb1.z, (v1.w - mean) * rstd * gv1.w + bb1.w);

        // ---- 16 dots, lane-partial (packed fma) ----
        float d[NS];
#pragma unroll
        for (int n = 0; n < NS; n++) {
            ull acc = 0ull;
            fma2(acc, qk2[n][0], xl2[0]);
            fma2(acc, qk2[n][1], xl2[1]);
            fma2(acc, qk2[n][2], xl2[2]);
            fma2(acc, qk2[n][3], xl2[3]);
            float lo, hi;
            unpack2(acc, lo, hi);
            d[n] = lo + hi;
        }

        // ---- halving butterfly: lane l ends with full sum of slot bitrev4(l&15) ----
#pragma unroll
        for (int i = 0; i < 8; i++) {
            const float sent = (lane & 1) ? d[i] : d[i + 8];
            const float recv = __shfl_xor_sync(0xffffffffu, sent, 1);
            d[i] = (lane & 1) ? d[i + 8] + recv : d[i] + recv;
        }
#pragma unroll
        for (int i = 0; i < 4; i++) {
            const float sent = (lane & 2) ? d[i] : d[i + 4];
            const float recv = __shfl_xor_sync(0xffffffffu, sent, 2);
            d[i] = (lane & 2) ? d[i + 4] + recv : d[i] + recv;
        }
#pragma unroll
        for (int i = 0; i < 2; i++) {
            const float sent = (lane & 4) ? d[i] : d[i + 2];
            const float recv = __shfl_xor_sync(0xffffffffu, sent, 4);
            d[i] = (lane & 4) ? d[i + 2] + recv : d[i] + recv;
        }
        {
            const float sent = (lane & 8) ? d[0] : d[1];
            const float recv = __shfl_xor_sync(0xffffffffu, sent, 8);
            d[0] = (lane & 8) ? d[1] + recv : d[0] + recv;
        }
        d[0] += __shfl_xor_sync(0xffffffffu, d[0], 16);
        float dd = d[0] + cn_r;

        // ---- softmax across the 16 slots (= lanes within a 16-group) ----
        float mx = dd;
        mx = fmaxf(mx, __shfl_xor_sync(0xffffffffu, mx, 1));
        mx = fmaxf(mx, __shfl_xor_sync(0xffffffffu, mx, 2));
        mx = fmaxf(mx, __shfl_xor_sync(0xffffffffu, mx, 4));
        mx = fmaxf(mx, __shfl_xor_sync(0xffffffffu, mx, 8));
        const float e = __expf(dd - mx);
        float ssum = e;
        ssum += __shfl_xor_sync(0xffffffffu, ssum, 1);
        ssum += __shfl_xor_sync(0xffffffffu, ssum, 2);
        ssum += __shfl_xor_sync(0xffffffffu, ssum, 4);
        ssum += __shfl_xor_sync(0xffffffffu, ssum, 8);
        const float a = __fdividef(e, ssum) + ATT_EPS;

        if (lane < 16) g_attn[(size_t)r * NS + sigma] = a;

        if (!more) break;
        r = rn;
        v0 = n0;
        v1 = n1;
    }
}

// ---------------- K_accum: re-LN rows, accumulate U (regs) and S; write block partials ----
__global__ void __launch_bounds__(256, 1)
k_accum(const float* __restrict__ x,
        const float* __restrict__ gin, const float* __restrict__ bin) {
    __shared__ __align__(16) float ublk[NS * D];
    __shared__ float sblk[8][NS];

    const int tid = threadIdx.x;
    const int lane = tid & 31;
    const int warp = tid >> 5;

    const float4* gin4 = reinterpret_cast<const float4*>(gin);
    const float4* bin4 = reinterpret_cast<const float4*>(bin);
    const float4 gv0 = gin4[lane], gv1 = gin4[lane + 32];
    const float4 bb0 = bin4[lane], bb1 = bin4[lane + 32];

    ull u2[NS][4];
#pragma unroll
    for (int n = 0; n < NS; n++)
#pragma unroll
        for (int p = 0; p < 4; p++) u2[n][p] = 0ull;
    float s_acc[NS];
#pragma unroll
    for (int n = 0; n < NS; n++) s_acc[n] = 0.0f;

    const float4* x4 = reinterpret_cast<const float4*>(x);
    const float4* ag4 = reinterpret_cast<const float4*>(g_attn);
    int r = blockIdx.x * 8 + warp;

    float4 v0 = x4[r * 64 + lane];
    float4 v1 = x4[r * 64 + 32 + lane];

    while (true) {
        const int rn = r + TOTW;
        const bool more = rn < B_ROWS;
        const int rl = more ? rn : r;
        const float4 n0 = x4[rl * 64 + lane];
        const float4 n1 = x4[rl * 64 + 32 + lane];

        // attn for this row (broadcast loads)
        const float4 af0 = ag4[r * 4 + 0];
        const float4 af1 = ag4[r * 4 + 1];
        const float4 af2 = ag4[r * 4 + 2];
        const float4 af3 = ag4[r * 4 + 3];

        // ---- LayerNorm in registers (identical to k_dots) ----
        float sm = v0.x + v0.y + v0.z + v0.w + v1.x + v1.y + v1.z + v1.w;
        float sq = v0.x * v0.x + v0.y * v0.y + v0.z * v0.z + v0.w * v0.w
                 + v1.x * v1.x + v1.y * v1.y + v1.z * v1.z + v1.w * v1.w;
        sm = warp_sum(sm);
        sq = warp_sum(sq);
        const float mean = sm * (1.0f / 256.0f);
        const float var = fmaxf(sq * (1.0f / 256.0f) - mean * mean, 0.0f);
        const float rstd = rsqrtf(var + LN_EPS);

        ull xl2[4];
        xl2[0] = pack2((v0.x - mean) * rstd * gv0.x + bb0.x, (v0.y - mean) * rstd * gv0.y + bb0.y);
        xl2[1] = pack2((v0.z - mean) * rstd * gv0.z + bb0.z, (v0.w - mean) * rstd * gv0.w + bb0.w);
        xl2[2] = pack2((v1.x - mean) * rstd * gv1.x + bb1.x, (v1.y - mean) * rstd * gv1.y + bb1.y);
        xl2[3] = pack2((v1.z - mean) * rstd * gv1.z + bb1.z, (v1.w - mean) * rstd * gv1.w + bb1.w);

        const float av[NS] = {af0.x, af0.y, af0.z, af0.w, af1.x, af1.y, af1.z, af1.w,
                              af2.x, af2.y, af2.z, af2.w, af3.x, af3.y, af3.z, af3.w};
#pragma unroll
        for (int n = 0; n < NS; n++) {
            s_acc[n] += av[n];
            const ull a2 = pack2(av[n], av[n]);
            fma2(u2[n][0], a2, xl2[0]);
            fma2(u2[n][1], a2, xl2[1]);
            fma2(u2[n][2], a2, xl2[2]);
            fma2(u2[n][3], a2, xl2[3]);
        }

        if (!more) break;
        r = rn;
        v0 = n0;
        v1 = n1;
    }

    // stage per-warp partials into shared (serialized, deterministic)
    for (int w = 0; w < 8; w++) {
        if (warp == w) {
#pragma unroll
            for (int n = 0; n < NS; n++) {
#pragma unroll
                for (int p = 0; p < 4; p++) {
                    float lo, hi;
                    unpack2(u2[n][p], lo, hi);
                    const int c = (p < 2) ? (lane * 4 + 2 * p) : (128 + lane * 4 + 2 * (p - 2));
                    if (w == 0) {
                        ublk[n * D + c] = lo;
                        ublk[n * D + c + 1] = hi;
                    } else {
                        ublk[n * D + c] += lo;
                        ublk[n * D + c + 1] += hi;
                    }
                }
            }
            if (lane == 0) {
#pragma unroll
                for (int n = 0; n < NS; n++) sblk[w][n] = s_acc[n];
            }
        }
        __syncthreads();
    }

    for (int i = tid; i < NS * D; i += 256)
        g_partU[(size_t)blockIdx.x * (NS * D) + i] = ublk[i];
    if (tid < NS) {
        float t = 0.0f;
#pragma unroll
        for (int w = 0; w < 8; w++) t += sblk[w][tid];
        g_partS[blockIdx.x * NS + tid] = t;
    }
}

// ---------------- K_post: reduce partials + Wv + GRU + LN + FFN + (next prep) ----------------
__global__ void k_post(const float* __restrict__ Wv, const float* __restrict__ bv,
                       const float* __restrict__ W_ih, const float* __restrict__ W_hh,
                       const float* __restrict__ b_ih, const float* __restrict__ b_hh,
                       const float* __restrict__ W1, const float* __restrict__ b1,
                       const float* __restrict__ W2, const float* __restrict__ b2,
                       const float* __restrict__ gf, const float* __restrict__ bef,
                       const float* __restrict__ Wq, const float* __restrict__ bq,
                       const float* __restrict__ Wk, const float* __restrict__ bk,
                       const float* __restrict__ gs, const float* __restrict__ bes,
                       float* __restrict__ out, int write_out, int do_prep) {
    __shared__ __align__(16) float un[D];
    __shared__ __align__(16) float up_s[D];
    __shared__ __align__(16) float h_s[D];
    __shared__ __align__(16) float tmp_s[D];
    __shared__ __align__(16) float s_sh[D];
    __shared__ __align__(16) float q_sh[D];
    __shared__ float red[32];
    const int n = blockIdx.x, t = threadIdx.x;

    // S
    const float sv = (t < GRID_MAIN) ? g_partS[t * NS + n] : 0.0f;
    const float S = block_sum256(sv, red);

    // U reduce over blocks (MLP-4)
    {
        float a0 = 0.0f, a1 = 0.0f, a2 = 0.0f, a3 = 0.0f;
        const int off = n * D + t;
#pragma unroll 4
        for (int k = 0; k < GRID_MAIN; k += 4) {
            a0 += g_partU[(size_t)(k + 0) * (NS * D) + off];
            a1 += g_partU[(size_t)(k + 1) * (NS * D) + off];
            a2 += g_partU[(size_t)(k + 2) * (NS * D) + off];
            a3 += g_partU[(size_t)(k + 3) * (NS * D) + off];
        }
        un[t] = ((a0 + a1) + (a2 + a3)) / S;
    }
    const float h = g_slots[n * D + t];
    h_s[t] = h;
    __syncthreads();

    // updates = Wv @ un + bv
    {
        const float4* w4 = reinterpret_cast<const float4*>(Wv + (size_t)t * D);
        const float4* u4 = reinterpret_cast<const float4*>(un);
        float acc = bv[t];
#pragma unroll 8
        for (int i = 0; i < D / 4; i++) acc += dot4(w4[i], u4[i]);
        up_s[t] = acc;
    }
    __syncthreads();

    // GRU
    const float4* u4 = reinterpret_cast<const float4*>(up_s);
    const float4* h4 = reinterpret_cast<const float4*>(h_s);
    float gx[3], gh[3];
#pragma unroll
    for (int gi = 0; gi < 3; gi++) {
        const float4* wx = reinterpret_cast<const float4*>(W_ih + (size_t)(gi * D + t) * D);
        const float4* wh = reinterpret_cast<const float4*>(W_hh + (size_t)(gi * D + t) * D);
        float ax = b_ih[gi * D + t];
        float ah = b_hh[gi * D + t];
#pragma unroll 4
        for (int i = 0; i < D / 4; i++) {
            ax += dot4(wx[i], u4[i]);
            ah += dot4(wh[i], h4[i]);
        }
        gx[gi] = ax;
        gh[gi] = ah;
    }
    const float rg = sigmoidf_(gx[0] + gh[0]);
    const float z = sigmoidf_(gx[1] + gh[1]);
    const float nn = tanhf(gx[2] + rg * gh[2]);
    const float hnew = (1.0f - z) * nn + z * h;

    // LN(hnew)
    const float m = block_sum256(hnew, red) * (1.0f / (float)D);
    const float dv = hnew - m;
    const float var = block_sum256(dv * dv, red) * (1.0f / (float)D);
    const float lnf = dv * rsqrtf(var + LN_EPS) * gf[t] + bef[t];
    tmp_s[t] = lnf;
    __syncthreads();

    // hidden = relu(W1 @ lnf + b1)
    float hd;
    {
        const float4* l4 = reinterpret_cast<const float4*>(tmp_s);
        const float4* w1r = reinterpret_cast<const float4*>(W1 + (size_t)t * D);
        float acc = b1[t];
#pragma unroll 8
        for (int i = 0; i < D / 4; i++) acc += dot4(w1r[i], l4[i]);
        hd = fmaxf(acc, 0.0f);
    }
    __syncthreads();
    tmp_s[t] = hd;
    __syncthreads();

    // o = W2 @ hidden + b2 ; res = hnew + o
    float res;
    {
        const float4* hh4 = reinterpret_cast<const float4*>(tmp_s);
        const float4* w2r = reinterpret_cast<const float4*>(W2 + (size_t)t * D);
        float acc = b2[t];
#pragma unroll 8
        for (int i = 0; i < D / 4; i++) acc += dot4(w2r[i], hh4[i]);
        res = hnew + acc;
    }
    g_slots[n * D + t] = res;
    if (write_out) out[n * D + t] = res;

    if (do_prep) {
        __syncthreads();
        prep_body(n, t, res, Wq, bq, Wk, bk, gs, bes, s_sh, q_sh, red);
    }
}

// ---------------- launch ----------------
extern "C" void kernel_launch(void* const* d_in, const int* in_sizes, int n_in,
                              void* d_out, int out_size) {
    const float* x      = (const float*)d_in[0];
    const float* noise  = (const float*)d_in[1];
    const float* mu     = (const float*)d_in[2];
    const float* sigma  = (const float*)d_in[3];
    const float* Wq     = (const float*)d_in[4];
    const float* bq     = (const float*)d_in[5];
    const float* Wk     = (const float*)d_in[6];
    const float* bk     = (const float*)d_in[7];
    const float* Wv     = (const float*)d_in[8];
    const float* bv     = (const float*)d_in[9];
    const float* W_ih   = (const float*)d_in[10];
    const float* W_hh   = (const float*)d_in[11];
    const float* b_ih   = (const float*)d_in[12];
    const float* b_hh   = (const float*)d_in[13];
    const float* W1     = (const float*)d_in[14];
    const float* b1     = (const float*)d_in[15];
    const float* W2     = (const float*)d_in[16];
    const float* b2     = (const float*)d_in[17];
    const float* g_in   = (const float*)d_in[18];
    const float* be_in  = (const float*)d_in[19];
    const float* g_s    = (const float*)d_in[20];
    const float* be_s   = (const float*)d_in[21];
    const float* g_f    = (const float*)d_in[22];
    const float* be_f   = (const float*)d_in[23];
    float* out = (float*)d_out;

    k_pre<<<NS, D>>>(noise, mu, sigma, Wq, bq, Wk, bk, g_s, be_s);
    for (int it = 0; it < 3; it++) {
        k_dots<<<GRID_MAIN, 256>>>(x, g_in, be_in);
        k_accum<<<GRID_MAIN, 256>>>(x, g_in, be_in);
        k_post<<<NS, D>>>(Wv, bv, W_ih, W_hh, b_ih, b_hh, W1, b1, W2, b2,
                          g_f, be_f, Wq, bq, Wk, bk, g_s, be_s,
                          out, it == 2 ? 1 : 0, it == 2 ? 0 : 1);
    }
}

// round 6
// speedup vs baseline: 1.3792x; 1.2796x over previous
#include <cuda_runtime.h>
#include <cuda_bf16.h>

#define D 256
#define NS 16
#define B_ROWS 131072
#define GRID_ACC 148
#define TOTW_ACC (GRID_ACC * 8)
#define GRID_DOTS 296
#define TOTW_DOTS (GRID_DOTS * 8)
#define LN_EPS 1e-5f
#define ATT_EPS 1e-8f
#define SCALE 0.0625f

typedef unsigned long long ull;

// ---------------- device scratch (static; no runtime allocation) ----------------
__device__ float g_xln[(size_t)B_ROWS * D];      // LN(x) materialized once
__device__ float g_WkT[D * D];                   // Wk transposed
__device__ float g_slots[NS * D];
__device__ float g_qk[NS * D];
__device__ float g_cn[NS];
__device__ float g_q[NS * D];
__device__ float g_attn[(size_t)B_ROWS * NS];
__device__ float g_partU[GRID_ACC * NS * D];
__device__ float g_partS[GRID_ACC * NS];
__device__ float g_updates[NS * D];
__device__ float g_gx[NS * 3 * D];
__device__ float g_gh[NS * 3 * D];
__device__ float g_hnew[NS * D];
__device__ float g_lnf[NS * D];
__device__ float g_hd[NS * D];

// ---------------- helpers ----------------
__device__ __forceinline__ float warp_sum(float v) {
    v += __shfl_xor_sync(0xffffffffu, v, 16);
    v += __shfl_xor_sync(0xffffffffu, v, 8);
    v += __shfl_xor_sync(0xffffffffu, v, 4);
    v += __shfl_xor_sync(0xffffffffu, v, 2);
    v += __shfl_xor_sync(0xffffffffu, v, 1);
    return v;
}

// blockDim.x == 256
__device__ __forceinline__ float block_sum256(float v, float* red) {
    const int lane = threadIdx.x & 31;
    const int w = threadIdx.x >> 5;
    v = warp_sum(v);
    if (lane == 0) red[w] = v;
    __syncthreads();
    if (w == 0) {
        float x = (lane < 8) ? red[lane] : 0.0f;
        x += __shfl_xor_sync(0xffffffffu, x, 4);
        x += __shfl_xor_sync(0xffffffffu, x, 2);
        x += __shfl_xor_sync(0xffffffffu, x, 1);
        if (lane == 0) red[0] = x;
    }
    __syncthreads();
    float r = red[0];
    __syncthreads();
    return r;
}

__device__ __forceinline__ float dot4(float4 a, float4 b) {
    return a.x * b.x + a.y * b.y + a.z * b.z + a.w * b.w;
}

__device__ __forceinline__ ull pack2(float lo, float hi) {
    ull r;
    asm("mov.b64 %0, {%1, %2};" : "=l"(r) : "f"(lo), "f"(hi));
    return r;
}
__device__ __forceinline__ void unpack2(ull v, float& lo, float& hi) {
    asm("mov.b64 {%0, %1}, %2;" : "=f"(lo), "=f"(hi) : "l"(v));
}
__device__ __forceinline__ void fma2(ull& d, ull a, ull b) {
    asm("fma.rn.f32x2 %0, %1, %2, %0;" : "+l"(d) : "l"(a), "l"(b));
}

__device__ __forceinline__ float sigmoidf_(float x) { return 1.0f / (1.0f + expf(-x)); }

// fc16 partial: thread (j, kq) dots W[j, kq*64 .. kq*64+63] with in_s; quad-reduced result
// valid in all 4 lanes of the quad.
__device__ __forceinline__ float fc_dot(const float* __restrict__ W, const float* in_s,
                                        int j, int kq) {
    const float4* w4 = reinterpret_cast<const float4*>(W + (size_t)j * D + kq * 64);
    const float4* s4 = reinterpret_cast<const float4*>(in_s + kq * 64);
    float a0 = 0.0f, a1 = 0.0f, a2 = 0.0f, a3 = 0.0f;
#pragma unroll
    for (int i = 0; i < 16; i += 4) {
        a0 += dot4(w4[i], s4[i]);
        a1 += dot4(w4[i + 1], s4[i + 1]);
        a2 += dot4(w4[i + 2], s4[i + 2]);
        a3 += dot4(w4[i + 3], s4[i + 3]);
    }
    float v = (a0 + a1) + (a2 + a3);
    v += __shfl_xor_sync(0xffffffffu, v, 1);
    v += __shfl_xor_sync(0xffffffffu, v, 2);
    return v;
}

// ---------------- K: materialize LN(x) once ----------------
__global__ void __launch_bounds__(256)
k_lnx(const float* __restrict__ x,
      const float* __restrict__ gin, const float* __restrict__ bin) {
    const int lane = threadIdx.x & 31;
    const int warp = threadIdx.x >> 5;
    const float4* gin4 = reinterpret_cast<const float4*>(gin);
    const float4* bin4 = reinterpret_cast<const float4*>(bin);
    const float4 gv0 = gin4[lane], gv1 = gin4[lane + 32];
    const float4 bb0 = bin4[lane], bb1 = bin4[lane + 32];

    const float4* x4 = reinterpret_cast<const float4*>(x);
    float4* o4 = reinterpret_cast<float4*>(g_xln);
    const int gw = blockIdx.x * 8 + warp;

    for (int r = gw; r < B_ROWS; r += 1024 * 8) {
        const float4 v0 = x4[(size_t)r * 64 + lane];
        const float4 v1 = x4[(size_t)r * 64 + 32 + lane];
        float sm = v0.x + v0.y + v0.z + v0.w + v1.x + v1.y + v1.z + v1.w;
        float sq = v0.x * v0.x + v0.y * v0.y + v0.z * v0.z + v0.w * v0.w
                 + v1.x * v1.x + v1.y * v1.y + v1.z * v1.z + v1.w * v1.w;
        sm = warp_sum(sm);
        sq = warp_sum(sq);
        const float mean = sm * (1.0f / 256.0f);
        const float var = fmaxf(sq * (1.0f / 256.0f) - mean * mean, 0.0f);
        const float rstd = rsqrtf(var + LN_EPS);
        float4 w0, w1;
        w0.x = (v0.x - mean) * rstd * gv0.x + bb0.x;
        w0.y = (v0.y - mean) * rstd * gv0.y + bb0.y;
        w0.z = (v0.z - mean) * rstd * gv0.z + bb0.z;
        w0.w = (v0.w - mean) * rstd * gv0.w + bb0.w;
        w1.x = (v1.x - mean) * rstd * gv1.x + bb1.x;
        w1.y = (v1.y - mean) * rstd * gv1.y + bb1.y;
        w1.z = (v1.z - mean) * rstd * gv1.z + bb1.z;
        w1.w = (v1.w - mean) * rstd * gv1.w + bb1.w;
        o4[(size_t)r * 64 + lane] = w0;
        o4[(size_t)r * 64 + 32 + lane] = w1;
    }
}

// ---------------- K: transpose Wk (once) ----------------
__global__ void k_wkT(const float* __restrict__ Wk) {
    __shared__ float tile[32][33];
    const int tx = threadIdx.x, ty = threadIdx.y;
    const int xi = blockIdx.x * 32 + tx;
#pragma unroll
    for (int r = 0; r < 32; r += 8)
        tile[ty + r][tx] = Wk[(size_t)(blockIdx.y * 32 + ty + r) * D + xi];
    __syncthreads();
    const int xo = blockIdx.y * 32 + tx;
#pragma unroll
    for (int r = 0; r < 32; r += 8)
        g_WkT[(size_t)(blockIdx.x * 32 + ty + r) * D + xo] = tile[tx][ty + r];
}

// ---------------- K: slots init ----------------
__global__ void k_init_slots(const float* __restrict__ noise,
                             const float* __restrict__ mu,
                             const float* __restrict__ sigma) {
    const int n = blockIdx.x, t = threadIdx.x;
    g_slots[n * D + t] = mu[t] + sigma[t] * noise[n * D + t];
}

// ---------------- K: s = LN(slots); q = Wq@s + bq ----------------
__global__ void k_lnq(const float* __restrict__ Wq, const float* __restrict__ bq,
                      const float* __restrict__ gs, const float* __restrict__ bes) {
    __shared__ __align__(16) float s_sh[D];
    __shared__ float red[32];
    const int n = blockIdx.x, t = threadIdx.x;

    const float sv = g_slots[n * D + t];
    const float m = block_sum256(sv, red) * (1.0f / (float)D);
    const float dv = sv - m;
    const float var = block_sum256(dv * dv, red) * (1.0f / (float)D);
    s_sh[t] = dv * rsqrtf(var + LN_EPS) * gs[t] + bes[t];
    __syncthreads();

    const float4* w4 = reinterpret_cast<const float4*>(Wq + (size_t)t * D);
    const float4* s4 = reinterpret_cast<const float4*>(s_sh);
    float a0 = bq[t], a1 = 0.0f, a2 = 0.0f, a3 = 0.0f;
#pragma unroll 4
    for (int i = 0; i < D / 4; i += 4) {
        a0 += dot4(w4[i], s4[i]);
        a1 += dot4(w4[i + 1], s4[i + 1]);
        a2 += dot4(w4[i + 2], s4[i + 2]);
        a3 += dot4(w4[i + 3], s4[i + 3]);
    }
    g_q[n * D + t] = (a0 + a1) + (a2 + a3);
}

// ---------------- K: qk = SCALE * q @ WkT ; cn = SCALE * q.bk ----------------
__global__ void k_qk(const float* __restrict__ bk) {
    __shared__ __align__(16) float in_s[D];
    __shared__ float red[32];
    const int n = blockIdx.x, tid = threadIdx.x;
    in_s[tid] = g_q[n * D + tid];
    __syncthreads();

    const int j = blockIdx.y * 64 + (tid >> 2);
    const int kq = tid & 3;
    const float v = fc_dot(g_WkT, in_s, j, kq);
    if (kq == 0) g_qk[n * D + j] = v * SCALE;

    if (blockIdx.y == 0) {
        const float p = block_sum256(in_s[tid] * bk[tid], red);
        if (tid == 0) g_cn[n] = p * SCALE;
    }
}

// ---------------- K: dots + softmax -> attn ----------------
__global__ void __launch_bounds__(256, 2)
k_dots() {
    __shared__ __align__(16) float qk_s[NS * D];
    __shared__ float cn_s[NS];

    const int tid = threadIdx.x;
    const int lane = tid & 31;
    const int warp = tid >> 5;
    const int sigma = __brev((unsigned)(lane & 15)) >> 28;  // bitrev4

    for (int i = tid; i < NS * D; i += 256) qk_s[i] = g_qk[i];
    if (tid < NS) cn_s[tid] = g_cn[tid];
    __syncthreads();
    const float cn_r = cn_s[sigma];

    const float4* x4 = reinterpret_cast<const float4*>(g_xln);
    const float4* qk4 = reinterpret_cast<const float4*>(qk_s);
    int r = blockIdx.x * 8 + warp;
    if (r >= B_ROWS) return;

    float4 v0 = x4[(size_t)r * 64 + lane];
    float4 v1 = x4[(size_t)r * 64 + 32 + lane];

    while (true) {
        const int rn = r + TOTW_DOTS;
        const bool more = rn < B_ROWS;
        const size_t rl = more ? (size_t)rn : (size_t)r;
        const float4 n0 = x4[rl * 64 + lane];
        const float4 n1 = x4[rl * 64 + 32 + lane];

        const ull xl0 = pack2(v0.x, v0.y), xl1 = pack2(v0.z, v0.w);
        const ull xl2 = pack2(v1.x, v1.y), xl3 = pack2(v1.z, v1.w);

        float d[NS];
#pragma unroll
        for (int n = 0; n < NS; n++) {
            const float4 qa = qk4[n * 64 + lane];
            const float4 qb = qk4[n * 64 + 32 + lane];
            ull acc = 0ull;
            fma2(acc, pack2(qa.x, qa.y), xl0);
            fma2(acc, pack2(qa.z, qa.w), xl1);
            fma2(acc, pack2(qb.x, qb.y), xl2);
            fma2(acc, pack2(qb.z, qb.w), xl3);
            float lo, hi;
            unpack2(acc, lo, hi);
            d[n] = lo + hi;
        }

        // halving butterfly: lane l ends with full sum of slot bitrev4(l&15)
#pragma unroll
        for (int i = 0; i < 8; i++) {
            const float sent = (lane & 1) ? d[i] : d[i + 8];
            const float recv = __shfl_xor_sync(0xffffffffu, sent, 1);
            d[i] = (lane & 1) ? d[i + 8] + recv : d[i] + recv;
        }
#pragma unroll
        for (int i = 0; i < 4; i++) {
            const float sent = (lane & 2) ? d[i] : d[i + 4];
            const float recv = __shfl_xor_sync(0xffffffffu, sent, 2);
            d[i] = (lane & 2) ? d[i + 4] + recv : d[i] + recv;
        }
#pragma unroll
        for (int i = 0; i < 2; i++) {
            const float sent = (lane & 4) ? d[i] : d[i + 2];
            const float recv = __shfl_xor_sync(0xffffffffu, sent, 4);
            d[i] = (lane & 4) ? d[i + 2] + recv : d[i] + recv;
        }
        {
            const float sent = (lane & 8) ? d[0] : d[1];
            const float recv = __shfl_xor_sync(0xffffffffu, sent, 8);
            d[0] = (lane & 8) ? d[1] + recv : d[0] + recv;
        }
        d[0] += __shfl_xor_sync(0xffffffffu, d[0], 16);
        const float dd = d[0] + cn_r;

        // softmax across the 16 slots (= lanes within a 16-group)
        float mx = dd;
        mx = fmaxf(mx, __shfl_xor_sync(0xffffffffu, mx, 1));
        mx = fmaxf(mx, __shfl_xor_sync(0xffffffffu, mx, 2));
        mx = fmaxf(mx, __shfl_xor_sync(0xffffffffu, mx, 4));
        mx = fmaxf(mx, __shfl_xor_sync(0xffffffffu, mx, 8));
        const float e = __expf(dd - mx);
        float ssum = e;
        ssum += __shfl_xor_sync(0xffffffffu, ssum, 1);
        ssum += __shfl_xor_sync(0xffffffffu, ssum, 2);
        ssum += __shfl_xor_sync(0xffffffffu, ssum, 4);
        ssum += __shfl_xor_sync(0xffffffffu, ssum, 8);
        const float a = __fdividef(e, ssum) + ATT_EPS;

        if (lane < 16) g_attn[(size_t)r * NS + sigma] = a;

        if (!more) break;
        r = rn;
        v0 = n0;
        v1 = n1;
    }
}

// ---------------- K: accumulate U, S over rows ----------------
__global__ void __launch_bounds__(256, 1)
k_accum() {
    __shared__ __align__(16) float ublk[NS * D];
    __shared__ float sblk[8][NS];

    const int tid = threadIdx.x;
    const int lane = tid & 31;
    const int warp = tid >> 5;

    ull u2[NS][4];
#pragma unroll
    for (int n = 0; n < NS; n++)
#pragma unroll
        for (int p = 0; p < 4; p++) u2[n][p] = 0ull;
    float s_acc[NS];
#pragma unroll
    for (int n = 0; n < NS; n++) s_acc[n] = 0.0f;

    const float4* x4 = reinterpret_cast<const float4*>(g_xln);
    const float4* ag4 = reinterpret_cast<const float4*>(g_attn);
    int r = blockIdx.x * 8 + warp;

    float4 v0 = x4[(size_t)r * 64 + lane];
    float4 v1 = x4[(size_t)r * 64 + 32 + lane];

    while (true) {
        const int rn = r + TOTW_ACC;
        const bool more = rn < B_ROWS;
        const size_t rl = more ? (size_t)rn : (size_t)r;
        const float4 n0 = x4[rl * 64 + lane];
        const float4 n1 = x4[rl * 64 + 32 + lane];

        const float4 af0 = ag4[(size_t)r * 4 + 0];
        const float4 af1 = ag4[(size_t)r * 4 + 1];
        const float4 af2 = ag4[(size_t)r * 4 + 2];
        const float4 af3 = ag4[(size_t)r * 4 + 3];

        const ull xl0 = pack2(v0.x, v0.y), xl1 = pack2(v0.z, v0.w);
        const ull xl2 = pack2(v1.x, v1.y), xl3 = pack2(v1.z, v1.w);

        const float av[NS] = {af0.x, af0.y, af0.z, af0.w, af1.x, af1.y, af1.z, af1.w,
                              af2.x, af2.y, af2.z, af2.w, af3.x, af3.y, af3.z, af3.w};
#pragma unroll
        for (int n = 0; n < NS; n++) {
            s_acc[n] += av[n];
            const ull a2 = pack2(av[n], av[n]);
            fma2(u2[n][0], a2, xl0);
            fma2(u2[n][1], a2, xl1);
            fma2(u2[n][2], a2, xl2);
            fma2(u2[n][3], a2, xl3);
        }

        if (!more) break;
        r = rn;
        v0 = n0;
        v1 = n1;
    }

    for (int w = 0; w < 8; w++) {
        if (warp == w) {
#pragma unroll
            for (int n = 0; n < NS; n++) {
#pragma unroll
                for (int p = 0; p < 4; p++) {
                    float lo, hi;
                    unpack2(u2[n][p], lo, hi);
                    const int c = (p < 2) ? (lane * 4 + 2 * p) : (128 + lane * 4 + 2 * (p - 2));
                    if (w == 0) {
                        ublk[n * D + c] = lo;
                        ublk[n * D + c + 1] = hi;
                    } else {
                        ublk[n * D + c] += lo;
                        ublk[n * D + c + 1] += hi;
                    }
                }
            }
            if (lane == 0) {
#pragma unroll
                for (int n = 0; n < NS; n++) sblk[w][n] = s_acc[n];
            }
        }
        __syncthreads();
    }

    for (int i = tid; i < NS * D; i += 256)
        g_partU[(size_t)blockIdx.x * (NS * D) + i] = ublk[i];
    if (tid < NS) {
        float t = 0.0f;
#pragma unroll
        for (int w = 0; w < 8; w++) t += sblk[w][tid];
        g_partS[blockIdx.x * NS + tid] = t;
    }
}

// ---------------- K: reduce partials + Wv -> updates ----------------
__global__ void k_upd(const float* __restrict__ Wv, const float* __restrict__ bv) {
    __shared__ __align__(16) float un[D];
    __shared__ float red[32];
    const int n = blockIdx.x, tid = threadIdx.x;

    // U reduce (unnormalized)
    {
        float a0 = 0.0f, a1 = 0.0f, a2 = 0.0f, a3 = 0.0f;
        const int off = n * D + tid;
#pragma unroll 4
        for (int k = 0; k < GRID_ACC; k += 4) {
            a0 += g_partU[(size_t)(k + 0) * (NS * D) + off];
            a1 += g_partU[(size_t)(k + 1) * (NS * D) + off];
            a2 += g_partU[(size_t)(k + 2) * (NS * D) + off];
            a3 += g_partU[(size_t)(k + 3) * (NS * D) + off];
        }
        un[tid] = (a0 + a1) + (a2 + a3);
    }
    const float sv = (tid < GRID_ACC) ? g_partS[tid * NS + n] : 0.0f;
    const float S = block_sum256(sv, red);  // includes syncthreads -> un visible

    const int j = blockIdx.y * 64 + (tid >> 2);
    const int kq = tid & 3;
    const float v = fc_dot(Wv, un, j, kq);
    if (kq == 0) g_updates[n * D + j] = v / S + bv[j];
}

// ---------------- K: GRU gates (gx via W_ih, gh via W_hh) ----------------
__global__ void k_gates(const float* __restrict__ W_ih, const float* __restrict__ W_hh,
                        const float* __restrict__ b_ih, const float* __restrict__ b_hh) {
    __shared__ __align__(16) float in_s[D];
    const int n = blockIdx.x, y = blockIdx.y, tid = threadIdx.x;
    const bool is_x = (y < 12);
    const float* in = is_x ? (g_updates + n * D) : (g_slots + n * D);
    const float* W = is_x ? W_ih : W_hh;
    const float* bias = is_x ? b_ih : b_hh;
    float* out = is_x ? g_gx : g_gh;
    const int jbase = (is_x ? y : (y - 12)) * 64;

    in_s[tid] = in[tid];
    __syncthreads();

    const int j = jbase + (tid >> 2);
    const int kq = tid & 3;
    const float v = fc_dot(W, in_s, j, kq);
    if (kq == 0) out[n * 3 * D + j] = v + bias[j];
}

// ---------------- K: GRU combine + LN ----------------
__global__ void k_gru_ln(const float* __restrict__ gf, const float* __restrict__ bef) {
    __shared__ float red[32];
    const int n = blockIdx.x, t = threadIdx.x;
    const float xr = g_gx[n * 3 * D + t];
    const float xz = g_gx[n * 3 * D + D + t];
    const float xn = g_gx[n * 3 * D + 2 * D + t];
    const float hr = g_gh[n * 3 * D + t];
    const float hz = g_gh[n * 3 * D + D + t];
    const float hn = g_gh[n * 3 * D + 2 * D + t];
    const float h = g_slots[n * D + t];

    const float r = sigmoidf_(xr + hr);
    const float z = sigmoidf_(xz + hz);
    const float nn = tanhf(xn + r * hn);
    const float hnew = (1.0f - z) * nn + z * h;

    const float m = block_sum256(hnew, red) * (1.0f / (float)D);
    const float dv = hnew - m;
    const float var = block_sum256(dv * dv, red) * (1.0f / (float)D);
    const float lnf = dv * rsqrtf(var + LN_EPS) * gf[t] + bef[t];

    g_hnew[n * D + t] = hnew;
    g_lnf[n * D + t] = lnf;
}

// ---------------- K: FFN layer 1 (relu) ----------------
__global__ void k_ff1(const float* __restrict__ W1, const float* __restrict__ b1) {
    __shared__ __align__(16) float in_s[D];
    const int n = blockIdx.x, tid = threadIdx.x;
    in_s[tid] = g_lnf[n * D + tid];
    __syncthreads();
    const int j = blockIdx.y * 64 + (tid >> 2);
    const int kq = tid & 3;
    const float v = fc_dot(W1, in_s, j, kq);
    if (kq == 0) g_hd[n * D + j] = fmaxf(v + b1[j], 0.0f);
}

// ---------------- K: FFN layer 2 + residual -> slots (+out) ----------------
__global__ void k_ff2(const float* __restrict__ W2, const float* __restrict__ b2,
                      float* __restrict__ out, int write_out) {
    __shared__ __align__(16) float in_s[D];
    const int n = blockIdx.x, tid = threadIdx.x;
    in_s[tid] = g_hd[n * D + tid];
    __syncthreads();
    const int j = blockIdx.y * 64 + (tid >> 2);
    const int kq = tid & 3;
    const float v = fc_dot(W2, in_s, j, kq);
    if (kq == 0) {
        const float res = g_hnew[n * D + j] + v + b2[j];
        g_slots[n * D + j] = res;
        if (write_out) out[n * D + j] = res;
    }
}

// ---------------- launch ----------------
extern "C" void kernel_launch(void* const* d_in, const int* in_sizes, int n_in,
                              void* d_out, int out_size) {
    const float* x      = (const float*)d_in[0];
    const float* noise  = (const float*)d_in[1];
    const float* mu     = (const float*)d_in[2];
    const float* sigma  = (const float*)d_in[3];
    const float* Wq     = (const float*)d_in[4];
    const float* bq     = (const float*)d_in[5];
    const float* Wk     = (const float*)d_in[6];
    const float* bk     = (const float*)d_in[7];
    const float* Wv     = (const float*)d_in[8];
    const float* bv     = (const float*)d_in[9];
    const float* W_ih   = (const float*)d_in[10];
    const float* W_hh   = (const float*)d_in[11];
    const float* b_ih   = (const float*)d_in[12];
    const float* b_hh   = (const float*)d_in[13];
    const float* W1     = (const float*)d_in[14];
    const float* b1     = (const float*)d_in[15];
    const float* W2     = (const float*)d_in[16];
    const float* b2     = (const float*)d_in[17];
    const float* g_in   = (const float*)d_in[18];
    const float* be_in  = (const float*)d_in[19];
    const float* g_s    = (const float*)d_in[20];
    const float* be_s   = (const float*)d_in[21];
    const float* g_f    = (const float*)d_in[22];
    const float* be_f   = (const float*)d_in[23];
    float* out = (float*)d_out;

    k_lnx<<<1024, 256>>>(x, g_in, be_in);
    k_wkT<<<dim3(8, 8), dim3(32, 8)>>>(Wk);
    k_init_slots<<<NS, D>>>(noise, mu, sigma);
    k_lnq<<<NS, D>>>(Wq, bq, g_s, be_s);
    k_qk<<<dim3(NS, 4), 256>>>(bk);

    for (int it = 0; it < 3; it++) {
        k_dots<<<GRID_DOTS, 256>>>();
        k_accum<<<GRID_ACC, 256>>>();
        k_upd<<<dim3(NS, 4), 256>>>(Wv, bv);
        k_gates<<<dim3(NS, 24), 256>>>(W_ih, W_hh, b_ih, b_hh);
        k_gru_ln<<<NS, D>>>(g_f, be_f);
        k_ff1<<<dim3(NS, 4), 256>>>(W1, b1);
        k_ff2<<<dim3(NS, 4), 256>>>(W2, b2, out, it == 2 ? 1 : 0);
        if (it < 2) {
            k_lnq<<<NS, D>>>(Wq, bq, g_s, be_s);
            k_qk<<<dim3(NS, 4), 256>>>(bk);
        }
    }
}